// round 7
// baseline (speedup 1.0000x reference)
#include <cuda_runtime.h>
#include <cuda_bf16.h>
#include <cstdint>

// ---------------------------------------------------------------------------
// Problem constants (B=16, 56x56x384, 12 heads, 7x7 windows, shift 3)
// ---------------------------------------------------------------------------
constexpr int IMG   = 56;
constexpr int C     = 384;
constexpr int NH    = 12;
constexpr int HD    = 32;
constexpr int WS    = 7;
constexpr int SHF   = 3;
constexpr int NWIN1 = 8;
constexpr int NT    = WS * WS;            // 49
constexpr int NWTOT = 16 * 64;            // 1024 windows
constexpr int MROWS = 16 * IMG * IMG;     // 50176
constexpr int NQKV  = 3 * C;              // 1152

// ---------------------------------------------------------------------------
// Device-global scratch (no runtime allocation allowed)
// ---------------------------------------------------------------------------
__device__ float          g_qkv[(size_t)MROWS * NQKV];
__device__ __nv_bfloat16  g_xhi[(size_t)MROWS * C];
__device__ __nv_bfloat16  g_xlo[(size_t)MROWS * C];
__device__ __nv_bfloat16  g_ahi[(size_t)MROWS * C];
__device__ __nv_bfloat16  g_alo[(size_t)MROWS * C];
__device__ __nv_bfloat16  g_wqh[(size_t)NQKV * C];
__device__ __nv_bfloat16  g_wql[(size_t)NQKV * C];
__device__ __nv_bfloat16  g_wph[(size_t)C * C];
__device__ __nv_bfloat16  g_wpl[(size_t)C * C];

// ---------------------------------------------------------------------------
// Portable PTX helpers (sm_80-level, valid for compute_103)
// ---------------------------------------------------------------------------
__device__ __forceinline__ uint32_t smem_u32(const void* p) {
    uint32_t a;
    asm("{ .reg .u64 t; cvta.to.shared.u64 t, %1; cvt.u32.u64 %0, t; }"
        : "=r"(a) : "l"(p));
    return a;
}
__device__ __forceinline__ void ldsm_x4(uint32_t& r0, uint32_t& r1,
                                        uint32_t& r2, uint32_t& r3, uint32_t addr) {
    asm volatile("ldmatrix.sync.aligned.m8n8.x4.shared.b16 {%0,%1,%2,%3}, [%4];"
                 : "=r"(r0), "=r"(r1), "=r"(r2), "=r"(r3) : "r"(addr));
}
__device__ __forceinline__ void mma16816(float* d, const uint32_t* a, const uint32_t* b) {
    asm volatile(
        "mma.sync.aligned.m16n8k16.row.col.f32.bf16.bf16.f32 "
        "{%0,%1,%2,%3}, {%4,%5,%6,%7}, {%8,%9}, {%0,%1,%2,%3};"
        : "+f"(d[0]), "+f"(d[1]), "+f"(d[2]), "+f"(d[3])
        : "r"(a[0]), "r"(a[1]), "r"(a[2]), "r"(a[3]), "r"(b[0]), "r"(b[1]));
}
#define CP_ASYNC16(dst, src) \
    asm volatile("cp.async.cg.shared.global [%0], [%1], 16;" :: "r"(dst), "l"(src))
#define CP_COMMIT()  asm volatile("cp.async.commit_group;")
#define CP_WAIT(N)   asm volatile("cp.async.wait_group %0;" :: "n"(N))

// SW64 swizzle for 64-byte rows
__device__ __forceinline__ uint32_t sw64(uint32_t o) { return o ^ ((o >> 3) & 0x30); }

// ---------------------------------------------------------------------------
// fp32 -> bf16 hi/lo split (x = hi + lo)
// ---------------------------------------------------------------------------
__global__ void conv_split4(const float4* __restrict__ src,
                            __nv_bfloat16* __restrict__ hi,
                            __nv_bfloat16* __restrict__ lo, int n4) {
    int i = blockIdx.x * blockDim.x + threadIdx.x;
    if (i >= n4) return;
    float4 v = src[i];
    float vv[4] = {v.x, v.y, v.z, v.w};
    __nv_bfloat16 h[4], l[4];
#pragma unroll
    for (int j = 0; j < 4; j++) {
        h[j] = __float2bfloat16(vv[j]);
        l[j] = __float2bfloat16(vv[j] - __bfloat162float(h[j]));
    }
    __nv_bfloat162* hp = (__nv_bfloat162*)(hi + (size_t)i * 4);
    __nv_bfloat162* lp = (__nv_bfloat162*)(lo + (size_t)i * 4);
    hp[0] = __nv_bfloat162(h[0], h[1]); hp[1] = __nv_bfloat162(h[2], h[3]);
    lp[0] = __nv_bfloat162(l[0], l[1]); lp[1] = __nv_bfloat162(l[2], l[3]);
}

// ---------------------------------------------------------------------------
// HMMA GEMM: out = (Ahi+Alo) @ (Bhi+Blo)^T + bias, 3 product passes per
// k-chunk. CTA tile 128x128, BK=32, cp.async 3-stage pipeline, 8 warps,
// warp tile 64x32. grid=(M/128, N/128), 256 threads, 2 CTAs/SM.
// Stage layout: [Ahi 8K][Alo 8K][Bhi 8K][Blo 8K] = 32KB, 3 stages = 96KB.
// ---------------------------------------------------------------------------
constexpr int STG  = 32768;
constexpr int NSTG = 3;
constexpr int NCH  = C / 32;   // 12

__global__ __launch_bounds__(256, 2) void mma_gemm(
    const __nv_bfloat16* __restrict__ Ahi, const __nv_bfloat16* __restrict__ Alo,
    const __nv_bfloat16* __restrict__ Bhi, const __nv_bfloat16* __restrict__ Blo,
    const float* __restrict__ bias, float* __restrict__ out, int ldout) {

    extern __shared__ __align__(128) char smem[];
    const uint32_t sb = smem_u32(smem);

    const int tid  = threadIdx.x;
    const int wid  = tid >> 5;
    const int lane = tid & 31;
    const int warp_m = wid >> 2;
    const int warp_n = wid & 3;

    const int m0 = blockIdx.x * 128;
    const int n0 = blockIdx.y * 128;

    // per-thread cp.async mapping: each tile is 128 rows x 64B = 512 16B units
    const int u0  = tid;
    const int u1  = tid + 256;
    const int r0_ = u0 >> 2, c0_ = (u0 & 3) * 16;
    const int r1_ = u1 >> 2, c1_ = (u1 & 3) * 16;
    const uint32_t st0 = sw64((uint32_t)(r0_ * 64 + c0_));
    const uint32_t st1 = sw64((uint32_t)(r1_ * 64 + c1_));

    const char* srcA[2] = {(const char*)(Ahi + (size_t)m0 * C),
                           (const char*)(Alo + (size_t)m0 * C)};
    const char* srcB[2] = {(const char*)(Bhi + (size_t)n0 * C),
                           (const char*)(Blo + (size_t)n0 * C)};

    auto issue_stage = [&](int ch, int buf) {
        const int kb = ch * 64;
        const uint32_t base = sb + buf * STG;
#pragma unroll
        for (int t = 0; t < 2; t++) {
            const char* a = srcA[t];
            const char* b = srcB[t];
            CP_ASYNC16(base + t * 8192 + st0,         a + (size_t)r0_ * (C * 2) + kb + c0_);
            CP_ASYNC16(base + t * 8192 + st1,         a + (size_t)r1_ * (C * 2) + kb + c1_);
            CP_ASYNC16(base + 16384 + t * 8192 + st0, b + (size_t)r0_ * (C * 2) + kb + c0_);
            CP_ASYNC16(base + 16384 + t * 8192 + st1, b + (size_t)r1_ * (C * 2) + kb + c1_);
        }
    };

    const int a_r = (lane & 7) + ((lane >> 3) & 1) * 8;
    const int a_c = (lane >> 4) * 16;
    const int b_r = ((lane >> 4) & 1) * 8 + (lane & 7);
    const int b_c = ((lane >> 3) & 1) * 16;

    float acc[4][4][4];
#pragma unroll
    for (int i = 0; i < 4; i++)
#pragma unroll
        for (int j = 0; j < 4; j++)
#pragma unroll
            for (int k = 0; k < 4; k++) acc[i][j][k] = 0.f;

    issue_stage(0, 0); CP_COMMIT();
    issue_stage(1, 1); CP_COMMIT();

    int buf = 0;
    for (int ch = 0; ch < NCH; ch++) {
        if (ch + 1 < NCH) { CP_WAIT(1); } else { CP_WAIT(0); }
        __syncthreads();
        if (ch + 2 < NCH) {
            int nb = buf + 2; if (nb >= NSTG) nb -= NSTG;
            issue_stage(ch + 2, nb);
            CP_COMMIT();
        }

        const uint32_t base = sb + buf * STG;
#pragma unroll
        for (int k16 = 0; k16 < 2; k16++) {
            const uint32_t kb = (uint32_t)(k16 * 32);
            uint32_t ah[4][4], al[4][4], bh[4][2], bl[4][2];
#pragma unroll
            for (int mt = 0; mt < 4; mt++) {
                int row = warp_m * 64 + mt * 16 + a_r;
                uint32_t so = sw64((uint32_t)(row * 64 + kb + a_c));
                ldsm_x4(ah[mt][0], ah[mt][1], ah[mt][2], ah[mt][3], base + so);
                ldsm_x4(al[mt][0], al[mt][1], al[mt][2], al[mt][3], base + 8192 + so);
            }
#pragma unroll
            for (int bt = 0; bt < 2; bt++) {
                int row = warp_n * 32 + bt * 16 + b_r;
                uint32_t so = sw64((uint32_t)(row * 64 + kb + b_c));
                ldsm_x4(bh[bt*2][0], bh[bt*2][1], bh[bt*2+1][0], bh[bt*2+1][1],
                        base + 16384 + so);
                ldsm_x4(bl[bt*2][0], bl[bt*2][1], bl[bt*2+1][0], bl[bt*2+1][1],
                        base + 24576 + so);
            }
#pragma unroll
            for (int mt = 0; mt < 4; mt++)
#pragma unroll
                for (int nt = 0; nt < 4; nt++) {
                    mma16816(acc[mt][nt], ah[mt], bh[nt]);
                    mma16816(acc[mt][nt], ah[mt], bl[nt]);
                    mma16816(acc[mt][nt], al[mt], bh[nt]);
                }
        }
        buf++; if (buf >= NSTG) buf = 0;
    }

    const int er = lane >> 2;
    const int ec = (lane & 3) * 2;
#pragma unroll
    for (int mt = 0; mt < 4; mt++) {
#pragma unroll
        for (int nt = 0; nt < 4; nt++) {
            int col = n0 + warp_n * 32 + nt * 8 + ec;
            float b0 = bias[col], b1 = bias[col + 1];
            int row0 = m0 + warp_m * 64 + mt * 16 + er;
            float2 v0 = {acc[mt][nt][0] + b0, acc[mt][nt][1] + b1};
            float2 v1 = {acc[mt][nt][2] + b0, acc[mt][nt][3] + b1};
            *(float2*)(out + (size_t)row0 * ldout + col)       = v0;
            *(float2*)(out + (size_t)(row0 + 8) * ldout + col) = v1;
        }
    }
}

// ---------------------------------------------------------------------------
// Attention per (head, window). One __syncthreads total. Scores held in
// registers; softmax via partner-lane shuffle; P@V register-accumulated.
// ---------------------------------------------------------------------------
__global__ __launch_bounds__(128) void attn_kernel(const float* __restrict__ table) {
    const int h    = blockIdx.x;
    const int wwin = blockIdx.y;

    __shared__ float qs[NT * HD];
    __shared__ float kk[NT * HD];
    __shared__ float vv[NT * HD];
    __shared__ float s[NT * 53];
    __shared__ float biasTab[169];
    __shared__ int   cnt[NT];
    __shared__ int   pix[NT];

    const int tid = threadIdx.x;
    const float scale = 0.17677669529663687f;   // 32^-0.5

    const int wi = wwin & 63;
    const int iw = wi >> 3, jw = wi & 7;
    if (tid < NT) {
        int r = tid / WS, c = tid - (tid / WS) * WS;
        int hh = iw * WS + r + SHF; if (hh >= IMG) hh -= IMG;
        int ww = jw * WS + c + SHF; if (ww >= IMG) ww -= IMG;
        pix[tid] = ((wwin >> 6) * IMG + hh) * IMG + ww;
        int ch = (iw < NWIN1 - 1) ? 0 : (r < WS - SHF ? 1 : 2);
        int cw = (jw < NWIN1 - 1) ? 0 : (c < WS - SHF ? 1 : 2);
        cnt[tid] = ch * 3 + cw;
    }
    for (int e = tid; e < 169; e += 128) biasTab[e] = table[e * NH + h];
    __syncthreads();

    // vectorized gather: 49 rows x 8 float4 per array
    for (int u = tid; u < NT * 8; u += 128) {
        int i = u >> 3, d4 = u & 7;
        const float4* row = (const float4*)(g_qkv + (size_t)pix[i] * NQKV + h * HD) + d4;
        float4 q4 = row[0];
        q4.x *= scale; q4.y *= scale; q4.z *= scale; q4.w *= scale;
        ((float4*)qs)[u] = q4;
        ((float4*)kk)[u] = row[C / 4];
        ((float4*)vv)[u] = row[2 * C / 4];
    }
    __syncthreads();

    // thread = (row i, half jh); clamp extra threads to row 48 (redundant work)
    int i  = tid >> 1; if (i >= NT) i = NT - 1;
    const int jh = tid & 1;
    const bool live = (tid >> 1) < NT;

    float q[32];
#pragma unroll
    for (int d4 = 0; d4 < 8; d4++) {
        float4 v = *(const float4*)(qs + i * HD + d4 * 4);
        q[d4*4+0] = v.x; q[d4*4+1] = v.y; q[d4*4+2] = v.z; q[d4*4+3] = v.w;
    }
    const int r1 = i / WS, c1 = i - r1 * WS;
    const int ci = cnt[i];
    const int j0 = jh ? 25 : 0;
    const int nj = jh ? 24 : 25;

    float sreg[25];
    float mx = -1e30f;
    for (int jj = 0; jj < nj; jj++) {
        const int j = j0 + jj;
        float acc = 0.f;
#pragma unroll
        for (int d4 = 0; d4 < 8; d4++) {
            float4 kv = *(const float4*)(kk + j * HD + d4 * 4);
            acc += q[d4*4+0] * kv.x + q[d4*4+1] * kv.y
                 + q[d4*4+2] * kv.z + q[d4*4+3] * kv.w;
        }
        int r2 = j / WS, c2 = j - r2 * WS;
        acc += biasTab[(r1 - r2 + WS - 1) * (2 * WS - 1) + (c1 - c2 + WS - 1)];
        if (ci != cnt[j]) acc -= 100.f;
        sreg[jj] = acc;
        mx = fmaxf(mx, acc);
    }
    // combine halves (partner = adjacent lane, same warp)
    mx = fmaxf(mx, __shfl_xor_sync(0xFFFFFFFFu, mx, 1));
    float sum = 0.f;
    for (int jj = 0; jj < nj; jj++) {
        float e = __expf(sreg[jj] - mx);
        sreg[jj] = e; sum += e;
    }
    sum += __shfl_xor_sync(0xFFFFFFFFu, sum, 1);
    const float inv = 1.f / sum;
    if (live) {
        for (int jj = 0; jj < nj; jj++) s[i * 53 + j0 + jj] = sreg[jj] * inv;
    }
    __syncwarp();

    // P@V: thread = (i, 16-wide d-half)
    const int dh = jh * 16;
    float acc[16];
#pragma unroll
    for (int k = 0; k < 16; k++) acc[k] = 0.f;
    for (int j = 0; j < NT; j++) {
        float pj = s[i * 53 + j];
#pragma unroll
        for (int d4 = 0; d4 < 4; d4++) {
            float4 v = *(const float4*)(vv + j * HD + dh + d4 * 4);
            acc[d4*4+0] += pj * v.x; acc[d4*4+1] += pj * v.y;
            acc[d4*4+2] += pj * v.z; acc[d4*4+3] += pj * v.w;
        }
    }
    if (live) {
        size_t off = (size_t)pix[i] * C + h * HD + dh;
        __nv_bfloat162* oh = (__nv_bfloat162*)(g_ahi + off);
        __nv_bfloat162* ol = (__nv_bfloat162*)(g_alo + off);
#pragma unroll
        for (int k = 0; k < 8; k++) {
            float a0 = acc[2*k], a1 = acc[2*k+1];
            __nv_bfloat16 h0 = __float2bfloat16(a0);
            __nv_bfloat16 h1 = __float2bfloat16(a1);
            oh[k] = __nv_bfloat162(h0, h1);
            ol[k] = __nv_bfloat162(__float2bfloat16(a0 - __bfloat162float(h0)),
                                   __float2bfloat16(a1 - __bfloat162float(h1)));
        }
    }
}

// ---------------------------------------------------------------------------
extern "C" void kernel_launch(void* const* d_in, const int* in_sizes, int n_in,
                              void* d_out, int out_size) {
    const float* x     = (const float*)d_in[0];
    const float* qkvw  = (const float*)d_in[1];
    const float* qkvb  = (const float*)d_in[2];
    const float* projw = (const float*)d_in[3];
    const float* projb = (const float*)d_in[4];
    const float* table = (const float*)d_in[5];
    float* out = (float*)d_out;

    void *p_qkv, *p_xhi, *p_xlo, *p_ahi, *p_alo, *p_wqh, *p_wql, *p_wph, *p_wpl;
    cudaGetSymbolAddress(&p_qkv, g_qkv);
    cudaGetSymbolAddress(&p_xhi, g_xhi);  cudaGetSymbolAddress(&p_xlo, g_xlo);
    cudaGetSymbolAddress(&p_ahi, g_ahi);  cudaGetSymbolAddress(&p_alo, g_alo);
    cudaGetSymbolAddress(&p_wqh, g_wqh);  cudaGetSymbolAddress(&p_wql, g_wql);
    cudaGetSymbolAddress(&p_wph, g_wph);  cudaGetSymbolAddress(&p_wpl, g_wpl);

    cudaFuncSetAttribute(mma_gemm, cudaFuncAttributeMaxDynamicSharedMemorySize, NSTG * STG);

    int n4x = (MROWS * C) / 4;
    conv_split4<<<(n4x + 255) / 256, 256>>>((const float4*)x,
        (__nv_bfloat16*)p_xhi, (__nv_bfloat16*)p_xlo, n4x);
    int n4q = (NQKV * C) / 4;
    conv_split4<<<(n4q + 255) / 256, 256>>>((const float4*)qkvw,
        (__nv_bfloat16*)p_wqh, (__nv_bfloat16*)p_wql, n4q);
    int n4p = (C * C) / 4;
    conv_split4<<<(n4p + 255) / 256, 256>>>((const float4*)projw,
        (__nv_bfloat16*)p_wph, (__nv_bfloat16*)p_wpl, n4p);

    mma_gemm<<<dim3(MROWS / 128, NQKV / 128), 256, NSTG * STG>>>(
        (const __nv_bfloat16*)p_xhi, (const __nv_bfloat16*)p_xlo,
        (const __nv_bfloat16*)p_wqh, (const __nv_bfloat16*)p_wql,
        qkvb, (float*)p_qkv, NQKV);

    attn_kernel<<<dim3(NH, NWTOT), 128>>>(table);

    mma_gemm<<<dim3(MROWS / 128, C / 128), 256, NSTG * STG>>>(
        (const __nv_bfloat16*)p_ahi, (const __nv_bfloat16*)p_alo,
        (const __nv_bfloat16*)p_wph, (const __nv_bfloat16*)p_wpl,
        projb, out, C);
}

// round 9
// speedup vs baseline: 1.0849x; 1.0849x over previous
#include <cuda_runtime.h>
#include <cuda_bf16.h>
#include <cstdint>

// ---------------------------------------------------------------------------
// Problem constants (B=16, 56x56x384, 12 heads, 7x7 windows, shift 3)
// ---------------------------------------------------------------------------
constexpr int IMG   = 56;
constexpr int C     = 384;
constexpr int NH    = 12;
constexpr int HD    = 32;
constexpr int WS    = 7;
constexpr int SHF   = 3;
constexpr int NWIN1 = 8;
constexpr int NT    = WS * WS;            // 49
constexpr int NWTOT = 16 * 64;            // 1024 windows
constexpr int MROWS = 16 * IMG * IMG;     // 50176
constexpr int NQKV  = 3 * C;              // 1152

// ---------------------------------------------------------------------------
// Device-global scratch (no runtime allocation allowed)
// ---------------------------------------------------------------------------
__device__ float          g_qkv[(size_t)MROWS * NQKV];
__device__ __nv_bfloat16  g_xhi[(size_t)MROWS * C];
__device__ __nv_bfloat16  g_xlo[(size_t)MROWS * C];
__device__ __nv_bfloat16  g_ahi[(size_t)MROWS * C];
__device__ __nv_bfloat16  g_alo[(size_t)MROWS * C];
__device__ __nv_bfloat16  g_wqh[(size_t)NQKV * C];
__device__ __nv_bfloat16  g_wql[(size_t)NQKV * C];
__device__ __nv_bfloat16  g_wph[(size_t)C * C];
__device__ __nv_bfloat16  g_wpl[(size_t)C * C];

// ---------------------------------------------------------------------------
// Portable PTX helpers (sm_80-level, valid for compute_103)
// ---------------------------------------------------------------------------
__device__ __forceinline__ uint32_t smem_u32(const void* p) {
    uint32_t a;
    asm("{ .reg .u64 t; cvta.to.shared.u64 t, %1; cvt.u32.u64 %0, t; }"
        : "=r"(a) : "l"(p));
    return a;
}
__device__ __forceinline__ void ldsm_x4(uint32_t& r0, uint32_t& r1,
                                        uint32_t& r2, uint32_t& r3, uint32_t addr) {
    asm volatile("ldmatrix.sync.aligned.m8n8.x4.shared.b16 {%0,%1,%2,%3}, [%4];"
                 : "=r"(r0), "=r"(r1), "=r"(r2), "=r"(r3) : "r"(addr));
}
__device__ __forceinline__ void mma16816(float* d, const uint32_t* a, const uint32_t* b) {
    asm volatile(
        "mma.sync.aligned.m16n8k16.row.col.f32.bf16.bf16.f32 "
        "{%0,%1,%2,%3}, {%4,%5,%6,%7}, {%8,%9}, {%0,%1,%2,%3};"
        : "+f"(d[0]), "+f"(d[1]), "+f"(d[2]), "+f"(d[3])
        : "r"(a[0]), "r"(a[1]), "r"(a[2]), "r"(a[3]), "r"(b[0]), "r"(b[1]));
}
#define CP_ASYNC16(dst, src) \
    asm volatile("cp.async.cg.shared.global [%0], [%1], 16;" :: "r"(dst), "l"(src))
#define CP_COMMIT()  asm volatile("cp.async.commit_group;")
#define CP_WAIT(N)   asm volatile("cp.async.wait_group %0;" :: "n"(N))

// SW64 swizzle for 64-byte rows
__device__ __forceinline__ uint32_t sw64(uint32_t o) { return o ^ ((o >> 3) & 0x30); }

// ---------------------------------------------------------------------------
// fp32 -> bf16 hi/lo split (x = hi + lo)
// ---------------------------------------------------------------------------
__global__ void conv_split4(const float4* __restrict__ src,
                            __nv_bfloat16* __restrict__ hi,
                            __nv_bfloat16* __restrict__ lo, int n4) {
    int i = blockIdx.x * blockDim.x + threadIdx.x;
    if (i >= n4) return;
    float4 v = src[i];
    float vv[4] = {v.x, v.y, v.z, v.w};
    __nv_bfloat16 h[4], l[4];
#pragma unroll
    for (int j = 0; j < 4; j++) {
        h[j] = __float2bfloat16(vv[j]);
        l[j] = __float2bfloat16(vv[j] - __bfloat162float(h[j]));
    }
    __nv_bfloat162* hp = (__nv_bfloat162*)(hi + (size_t)i * 4);
    __nv_bfloat162* lp = (__nv_bfloat162*)(lo + (size_t)i * 4);
    hp[0] = __nv_bfloat162(h[0], h[1]); hp[1] = __nv_bfloat162(h[2], h[3]);
    lp[0] = __nv_bfloat162(l[0], l[1]); lp[1] = __nv_bfloat162(l[2], l[3]);
}

// ---------------------------------------------------------------------------
// HMMA GEMM (R5 proven schedule): out = (Ahi+Alo)@(Bhi+Blo)^T + bias,
// 3 passes per k-chunk, CTA tile 128x128, BK=32, cp.async double-buffered
// with issue-before-wait. 8 warps, warp tile 64x32. 256 threads.
// ---------------------------------------------------------------------------
constexpr int STG = 32768;
constexpr int NCH = C / 32;   // 12

__global__ __launch_bounds__(256) void mma_gemm(
    const __nv_bfloat16* __restrict__ Ahi, const __nv_bfloat16* __restrict__ Alo,
    const __nv_bfloat16* __restrict__ Bhi, const __nv_bfloat16* __restrict__ Blo,
    const float* __restrict__ bias, float* __restrict__ out, int ldout) {

    extern __shared__ __align__(128) char smem[];
    const uint32_t sb = smem_u32(smem);

    const int tid  = threadIdx.x;
    const int wid  = tid >> 5;
    const int lane = tid & 31;
    const int warp_m = wid >> 2;
    const int warp_n = wid & 3;

    const int m0 = blockIdx.x * 128;
    const int n0 = blockIdx.y * 128;

    const int u0  = tid;
    const int u1  = tid + 256;
    const int r0_ = u0 >> 2, c0_ = (u0 & 3) * 16;
    const int r1_ = u1 >> 2, c1_ = (u1 & 3) * 16;
    const uint32_t st0 = sw64((uint32_t)(r0_ * 64 + c0_));
    const uint32_t st1 = sw64((uint32_t)(r1_ * 64 + c1_));

    const char* srcA[2] = {(const char*)(Ahi + (size_t)m0 * C),
                           (const char*)(Alo + (size_t)m0 * C)};
    const char* srcB[2] = {(const char*)(Bhi + (size_t)n0 * C),
                           (const char*)(Blo + (size_t)n0 * C)};

    auto issue_stage = [&](int ch, int buf) {
        const int kb = ch * 64;
        const uint32_t base = sb + buf * STG;
#pragma unroll
        for (int t = 0; t < 2; t++) {
            const char* a = srcA[t];
            const char* b = srcB[t];
            CP_ASYNC16(base + t * 8192 + st0,         a + (size_t)r0_ * (C * 2) + kb + c0_);
            CP_ASYNC16(base + t * 8192 + st1,         a + (size_t)r1_ * (C * 2) + kb + c1_);
            CP_ASYNC16(base + 16384 + t * 8192 + st0, b + (size_t)r0_ * (C * 2) + kb + c0_);
            CP_ASYNC16(base + 16384 + t * 8192 + st1, b + (size_t)r1_ * (C * 2) + kb + c1_);
        }
    };

    const int a_r = (lane & 7) + ((lane >> 3) & 1) * 8;
    const int a_c = (lane >> 4) * 16;
    const int b_r = ((lane >> 4) & 1) * 8 + (lane & 7);
    const int b_c = ((lane >> 3) & 1) * 16;

    float acc[4][4][4];
#pragma unroll
    for (int i = 0; i < 4; i++)
#pragma unroll
        for (int j = 0; j < 4; j++)
#pragma unroll
            for (int k = 0; k < 4; k++) acc[i][j][k] = 0.f;

    issue_stage(0, 0);
    CP_COMMIT();

    for (int ch = 0; ch < NCH; ch++) {
        const int buf = ch & 1;
        if (ch + 1 < NCH) {
            issue_stage(ch + 1, buf ^ 1);
            CP_COMMIT();
            CP_WAIT(1);
        } else {
            CP_WAIT(0);
        }
        __syncthreads();

        const uint32_t base = sb + buf * STG;
#pragma unroll
        for (int k16 = 0; k16 < 2; k16++) {
            const uint32_t kb = (uint32_t)(k16 * 32);
            uint32_t ah[4][4], al[4][4], bh[4][2], bl[4][2];
#pragma unroll
            for (int mt = 0; mt < 4; mt++) {
                int row = warp_m * 64 + mt * 16 + a_r;
                uint32_t so = sw64((uint32_t)(row * 64 + kb + a_c));
                ldsm_x4(ah[mt][0], ah[mt][1], ah[mt][2], ah[mt][3], base + so);
                ldsm_x4(al[mt][0], al[mt][1], al[mt][2], al[mt][3], base + 8192 + so);
            }
#pragma unroll
            for (int bt = 0; bt < 2; bt++) {
                int row = warp_n * 32 + bt * 16 + b_r;
                uint32_t so = sw64((uint32_t)(row * 64 + kb + b_c));
                ldsm_x4(bh[bt*2][0], bh[bt*2][1], bh[bt*2+1][0], bh[bt*2+1][1],
                        base + 16384 + so);
                ldsm_x4(bl[bt*2][0], bl[bt*2][1], bl[bt*2+1][0], bl[bt*2+1][1],
                        base + 24576 + so);
            }
#pragma unroll
            for (int mt = 0; mt < 4; mt++)
#pragma unroll
                for (int nt = 0; nt < 4; nt++) {
                    mma16816(acc[mt][nt], ah[mt], bh[nt]);
                    mma16816(acc[mt][nt], ah[mt], bl[nt]);
                    mma16816(acc[mt][nt], al[mt], bh[nt]);
                }
        }
        __syncthreads();
    }

    const int er = lane >> 2;
    const int ec = (lane & 3) * 2;
#pragma unroll
    for (int mt = 0; mt < 4; mt++) {
#pragma unroll
        for (int nt = 0; nt < 4; nt++) {
            int col = n0 + warp_n * 32 + nt * 8 + ec;
            float b0 = bias[col], b1 = bias[col + 1];
            int row0 = m0 + warp_m * 64 + mt * 16 + er;
            float2 v0 = {acc[mt][nt][0] + b0, acc[mt][nt][1] + b1};
            float2 v1 = {acc[mt][nt][2] + b0, acc[mt][nt][3] + b1};
            *(float2*)(out + (size_t)row0 * ldout + col)       = v0;
            *(float2*)(out + (size_t)(row0 + 8) * ldout + col) = v1;
        }
    }
}

// ---------------------------------------------------------------------------
// Attention per (head, window), crossbar-minimized:
//  - scores: thread j holds k_j in registers; q_i read via broadcast
//  - softmax: thread-per-row (conflict-free stride-53 columns)
//  - P@V: lane = dim d, 4 output rows per pass (V row reused 4x)
// ---------------------------------------------------------------------------
__global__ __launch_bounds__(128) void attn_kernel(const float* __restrict__ table) {
    const int h    = blockIdx.x;
    const int wwin = blockIdx.y;

    __shared__ float qs[NT * HD];       // row-major, stride 32
    __shared__ float kt[HD * 52];       // transposed K: kt[d*52 + j]
    __shared__ float vv[NT * HD];       // row-major, stride 32
    __shared__ float s[NT * 53];
    __shared__ float biasTab[169];
    __shared__ int   cnt[NT];
    __shared__ int   pix[NT];

    const int tid = threadIdx.x;
    const float scale = 0.17677669529663687f;   // 32^-0.5

    const int wi = wwin & 63;
    const int iw = wi >> 3, jw = wi & 7;
    if (tid < NT) {
        int r = tid / WS, c = tid - (tid / WS) * WS;
        int hh = iw * WS + r + SHF; if (hh >= IMG) hh -= IMG;
        int ww = jw * WS + c + SHF; if (ww >= IMG) ww -= IMG;
        pix[tid] = ((wwin >> 6) * IMG + hh) * IMG + ww;
        int ch = (iw < NWIN1 - 1) ? 0 : (r < WS - SHF ? 1 : 2);
        int cw = (jw < NWIN1 - 1) ? 0 : (c < WS - SHF ? 1 : 2);
        cnt[tid] = ch * 3 + cw;
    }
    for (int e = tid; e < 169; e += 128) biasTab[e] = table[e * NH + h];
    __syncthreads();

    // gather q (scaled), k (transposed), v
    for (int u = tid; u < NT * 8; u += 128) {
        int i = u >> 3, d4 = u & 7;
        const float4* row = (const float4*)(g_qkv + (size_t)pix[i] * NQKV + h * HD) + d4;
        float4 q4 = row[0];
        q4.x *= scale; q4.y *= scale; q4.z *= scale; q4.w *= scale;
        ((float4*)qs)[u] = q4;
        float4 k4 = row[C / 4];
        kt[(d4 * 4 + 0) * 52 + i] = k4.x;
        kt[(d4 * 4 + 1) * 52 + i] = k4.y;
        kt[(d4 * 4 + 2) * 52 + i] = k4.z;
        kt[(d4 * 4 + 3) * 52 + i] = k4.w;
        ((float4*)vv)[u] = row[2 * C / 4];
    }
    __syncthreads();

    // Phase A: scores. Thread j owns k_j (registers); q_i broadcast.
    if (tid < NT) {
        const int j = tid;
        float kr[32];
#pragma unroll
        for (int d = 0; d < 32; d++) kr[d] = kt[d * 52 + j];
        const int r2 = j / WS, c2 = j - r2 * WS;
        const int cj = cnt[j];
        for (int i = 0; i < NT; i++) {
            float acc = 0.f;
#pragma unroll
            for (int d4 = 0; d4 < 8; d4++) {
                float4 q4 = *(const float4*)(qs + i * HD + d4 * 4);
                acc += q4.x * kr[d4*4+0] + q4.y * kr[d4*4+1]
                     + q4.z * kr[d4*4+2] + q4.w * kr[d4*4+3];
            }
            int r1 = i / WS, c1 = i - r1 * WS;
            acc += biasTab[(r1 - r2 + WS - 1) * (2 * WS - 1) + (c1 - c2 + WS - 1)];
            if (cnt[i] != cj) acc -= 100.f;
            s[i * 53 + j] = acc;
        }
    }
    __syncthreads();

    // Softmax: thread per row (stride-53 -> conflict-free across lanes)
    if (tid < NT) {
        float* row = s + tid * 53;
        float mx = -1e30f;
#pragma unroll 7
        for (int j = 0; j < NT; j++) mx = fmaxf(mx, row[j]);
        float sum = 0.f;
#pragma unroll 7
        for (int j = 0; j < NT; j++) { float e = __expf(row[j] - mx); row[j] = e; sum += e; }
        float inv = 1.f / sum;
#pragma unroll 7
        for (int j = 0; j < NT; j++) row[j] *= inv;
    }
    __syncthreads();

    // Phase B: P@V. warp w, lane d. Rows i = w + 4*t, t = 0..12.
    const int w = tid >> 5;
    const int d = tid & 31;
    for (int t0 = 0; t0 < 13; t0 += 4) {
        float acc[4] = {0.f, 0.f, 0.f, 0.f};
        int iv[4];
#pragma unroll
        for (int tt = 0; tt < 4; tt++) {
            int i = w + 4 * (t0 + tt);
            iv[tt] = (t0 + tt < 13 && i < NT) ? i : -1;
        }
        int ic[4];
#pragma unroll
        for (int tt = 0; tt < 4; tt++) ic[tt] = (iv[tt] >= 0) ? iv[tt] : 0;

        for (int j = 0; j < NT; j++) {
            float v = vv[j * HD + d];
#pragma unroll
            for (int tt = 0; tt < 4; tt++)
                acc[tt] += s[ic[tt] * 53 + j] * v;
        }
#pragma unroll
        for (int tt = 0; tt < 4; tt++) {
            if (iv[tt] < 0) continue;
            size_t off = (size_t)pix[iv[tt]] * C + h * HD + d;
            float a = acc[tt];
            __nv_bfloat16 hv = __float2bfloat16(a);
            g_ahi[off] = hv;
            g_alo[off] = __float2bfloat16(a - __bfloat162float(hv));
        }
    }
}

// ---------------------------------------------------------------------------
extern "C" void kernel_launch(void* const* d_in, const int* in_sizes, int n_in,
                              void* d_out, int out_size) {
    const float* x     = (const float*)d_in[0];
    const float* qkvw  = (const float*)d_in[1];
    const float* qkvb  = (const float*)d_in[2];
    const float* projw = (const float*)d_in[3];
    const float* projb = (const float*)d_in[4];
    const float* table = (const float*)d_in[5];
    float* out = (float*)d_out;

    void *p_qkv, *p_xhi, *p_xlo, *p_ahi, *p_alo, *p_wqh, *p_wql, *p_wph, *p_wpl;
    cudaGetSymbolAddress(&p_qkv, g_qkv);
    cudaGetSymbolAddress(&p_xhi, g_xhi);  cudaGetSymbolAddress(&p_xlo, g_xlo);
    cudaGetSymbolAddress(&p_ahi, g_ahi);  cudaGetSymbolAddress(&p_alo, g_alo);
    cudaGetSymbolAddress(&p_wqh, g_wqh);  cudaGetSymbolAddress(&p_wql, g_wql);
    cudaGetSymbolAddress(&p_wph, g_wph);  cudaGetSymbolAddress(&p_wpl, g_wpl);

    cudaFuncSetAttribute(mma_gemm, cudaFuncAttributeMaxDynamicSharedMemorySize, 2 * STG);

    int n4x = (MROWS * C) / 4;
    conv_split4<<<(n4x + 255) / 256, 256>>>((const float4*)x,
        (__nv_bfloat16*)p_xhi, (__nv_bfloat16*)p_xlo, n4x);
    int n4q = (NQKV * C) / 4;
    conv_split4<<<(n4q + 255) / 256, 256>>>((const float4*)qkvw,
        (__nv_bfloat16*)p_wqh, (__nv_bfloat16*)p_wql, n4q);
    int n4p = (C * C) / 4;
    conv_split4<<<(n4p + 255) / 256, 256>>>((const float4*)projw,
        (__nv_bfloat16*)p_wph, (__nv_bfloat16*)p_wpl, n4p);

    mma_gemm<<<dim3(MROWS / 128, NQKV / 128), 256, 2 * STG>>>(
        (const __nv_bfloat16*)p_xhi, (const __nv_bfloat16*)p_xlo,
        (const __nv_bfloat16*)p_wqh, (const __nv_bfloat16*)p_wql,
        qkvb, (float*)p_qkv, NQKV);

    attn_kernel<<<dim3(NH, NWTOT), 128>>>(table);

    mma_gemm<<<dim3(MROWS / 128, C / 128), 256, 2 * STG>>>(
        (const __nv_bfloat16*)p_ahi, (const __nv_bfloat16*)p_alo,
        (const __nv_bfloat16*)p_wph, (const __nv_bfloat16*)p_wpl,
        projb, out, C);
}